// round 10
// baseline (speedup 1.0000x reference)
#include <cuda_runtime.h>
#include <cuda_bf16.h>
#include <cstdint>

#define IN_      512
#define OUT_     512
#define NB_      16
#define M_TOTAL  1024
#define TM       64
#define TN       64
#define NTHREADS 256
#define NCHUNK   (IN_ / 64)    // 8

// dynamic smem: 2 buffers x (Ah,Al,Bh,Bl planes of 8KB) + rows + bias
#define PLANE      8192
#define BUFSZ      (4 * PLANE)             // 32 KB
#define OFF_ROWS   (2 * BUFSZ)             // 65536
#define OFF_BIAS   (OFF_ROWS + M_TOTAL * 4)
#define SMEM_TOTAL (OFF_BIAS + TN * 4)     // 69888

// ---------------- PTX helpers ----------------
__device__ __forceinline__ uint32_t smem_u32(const void* p) {
    uint32_t a;
    asm("{ .reg .u64 t; cvta.to.shared.u64 t, %1; cvt.u32.u64 %0, t; }" : "=r"(a) : "l"(p));
    return a;
}
__device__ __forceinline__ void ldsm4(uint32_t* r, uint32_t addr) {
    asm volatile("ldmatrix.sync.aligned.m8n8.x4.shared.b16 {%0,%1,%2,%3}, [%4];"
        : "=r"(r[0]), "=r"(r[1]), "=r"(r[2]), "=r"(r[3]) : "r"(addr));
}
__device__ __forceinline__ void mma_bf16(float* c, const uint32_t* a, uint32_t b0, uint32_t b1) {
    asm volatile("mma.sync.aligned.m16n8k16.row.col.f32.bf16.bf16.f32 "
        "{%0,%1,%2,%3}, {%4,%5,%6,%7}, {%8,%9}, {%0,%1,%2,%3};"
        : "+f"(c[0]), "+f"(c[1]), "+f"(c[2]), "+f"(c[3])
        : "r"(a[0]), "r"(a[1]), "r"(a[2]), "r"(a[3]), "r"(b0), "r"(b1));
}

// cheap split: float4 -> packed bf16 hi pairs + lo (residual) pairs
// (numerics verified identical to intrinsic version in R7-R9: rel_err 4.877e-6)
__device__ __forceinline__ void split4(float4 v, uint2& hi, uint2& lo) {
    uint32_t h01, h23;
    asm("cvt.rn.bf16x2.f32 %0, %1, %2;" : "=r"(h01) : "f"(v.y), "f"(v.x));
    asm("cvt.rn.bf16x2.f32 %0, %1, %2;" : "=r"(h23) : "f"(v.w), "f"(v.z));
    float f0 = __uint_as_float(h01 << 16);
    float f1 = __uint_as_float(h01 & 0xFFFF0000u);
    float f2 = __uint_as_float(h23 << 16);
    float f3 = __uint_as_float(h23 & 0xFFFF0000u);
    uint32_t l01, l23;
    asm("cvt.rn.bf16x2.f32 %0, %1, %2;" : "=r"(l01) : "f"(v.y - f1), "f"(v.x - f0));
    asm("cvt.rn.bf16x2.f32 %0, %1, %2;" : "=r"(l23) : "f"(v.w - f3), "f"(v.z - f2));
    hi.x = h01; hi.y = h23; lo.x = l01; lo.y = l23;
}

// ---------------- fused binning + grouped GEMM (bf16-split HMMA) -------------
__global__ __launch_bounds__(NTHREADS, 2) void gemm_kernel(
    const float* __restrict__ x,      // (1024, IN)
    const int*   __restrict__ sel,    // (1024,)
    const float* __restrict__ w,      // (NB, OUT, IN)
    const float* __restrict__ bias,   // (NB, OUT)
    float* __restrict__ out)          // (1024, OUT)
{
    extern __shared__ __align__(128) uint8_t smem[];
    int*   rows_bank = (int*)(smem + OFF_ROWS);
    float* bias_s    = (float*)(smem + OFF_BIAS);
    __shared__ int warp_base[8];
    __shared__ int cnt_s;

    const int tid = threadIdx.x;
    const int lid = tid & 31, wid = tid >> 5;
    const int warp_m = wid & 3;        // 4 m-warps x 16 rows
    const int warp_n = wid >> 2;       // 2 n-warps x 32 cols
    const int g  = blockIdx.y;
    const int n0 = blockIdx.x * TN;
    const int mz = blockIdx.z;         // m-slice within bank

    // ---- deterministic binning (R9-verified stable compaction) ----
    {
        int4 sv = *(const int4*)&sel[tid * 4];
        int m0f = (sv.x == g), m1f = (sv.y == g), m2f = (sv.z == g), m3f = (sv.w == g);
        int lc = m0f + m1f + m2f + m3f;
        int inc = lc;
        #pragma unroll
        for (int d = 1; d < 32; d <<= 1) {
            int nv = __shfl_up_sync(0xffffffffu, inc, d);
            if (lid >= d) inc += nv;
        }
        if (lid == 31) warp_base[wid] = inc;
        __syncthreads();
        if (tid == 0) {
            int acc = 0;
            #pragma unroll
            for (int i = 0; i < 8; i++) { int v = warp_base[i]; warp_base[i] = acc; acc += v; }
            cnt_s = acc;
        }
        __syncthreads();
        int p = warp_base[wid] + inc - lc;
        if (m0f) rows_bank[p++] = tid * 4 + 0;
        if (m1f) rows_bank[p++] = tid * 4 + 1;
        if (m2f) rows_bank[p++] = tid * 4 + 2;
        if (m3f) rows_bank[p++] = tid * 4 + 3;
    }
    if (tid < TN) bias_s[tid] = bias[g * OUT_ + n0 + tid];
    __syncthreads();
    const int cnt = cnt_s;
    if (mz * TM >= cnt) return;

    const float* __restrict__ wg = w + (size_t)g * OUT_ * IN_;
    const uint32_t sm_b = smem_u32(smem);

    // ---- R5 staging geometry (conflict-free uint2 pattern) ----
    // rbase = tid>>4 (0..15), 4 rows per thread (stride 16), 4 floats each
    const int rbase = tid >> 4;
    const int c4    = (tid & 15) * 4;              // k offset (floats)
    const uint32_t st_sw = (uint32_t)((tid & 15) * 8) ^ (uint32_t)((rbase & 7) * 16);

    // ldmatrix constant address parts (R5-verified)
    const uint32_t swx   = (uint32_t)(lid & 7) * 16;
    const uint32_t khalf = (uint32_t)(lid >> 4) * 16;
    const uint32_t a_off  = (uint32_t)(warp_m * 16 + (lid & 15)) * 128;
    const uint32_t b0_off = (uint32_t)(warp_n * 32 + (lid & 15)) * 128;
    const uint32_t b1_off = b0_off + 16 * 128;

    const float4 f4z = make_float4(0.f, 0.f, 0.f, 0.f);

    for (int m0 = mz * TM; m0 < cnt; m0 += 2 * TM) {
        int rA[4];
        #pragma unroll
        for (int j = 0; j < 4; j++) {
            int m = m0 + rbase + j * 16;
            rA[j] = (m < cnt) ? rows_bank[m] : -1;
        }

        float4 av[4], bv[4];
        #pragma unroll
        for (int j = 0; j < 4; j++) {   // prefetch chunk 0
            int rowA = rbase + j * 16;
            av[j] = (rA[j] >= 0) ? *(const float4*)&x[(size_t)rA[j] * IN_ + c4] : f4z;
            bv[j] = *(const float4*)&wg[(size_t)(n0 + rowA) * IN_ + c4];
        }

        float acc[4][4] = {};

        #pragma unroll 1
        for (int t = 0; t < NCHUNK; t++) {
            uint8_t* bb = smem + (uint32_t)(t & 1) * BUFSZ;

            // ---- stage chunk t into bf16 hi/lo planes (R5 uint2 pattern) ----
            #pragma unroll
            for (int j = 0; j < 4; j++) {
                uint32_t soff = (uint32_t)((rbase + j * 16) * 128) + st_sw;
                uint2 hi, lo;
                split4(av[j], hi, lo);
                *(uint2*)(bb + soff)             = hi;   // Ah
                *(uint2*)(bb + PLANE + soff)     = lo;   // Al
                split4(bv[j], hi, lo);
                *(uint2*)(bb + 2 * PLANE + soff) = hi;   // Bh
                *(uint2*)(bb + 3 * PLANE + soff) = lo;   // Bl
            }
            __syncthreads();   // buf visible; all warps left compute(t-1)

            // ---- prefetch chunk t+1 (overlaps with MMA below) ----
            if (t < NCHUNK - 1) {
                int k0 = (t + 1) * 64 + c4;
                #pragma unroll
                for (int j = 0; j < 4; j++) {
                    int rowA = rbase + j * 16;
                    av[j] = (rA[j] >= 0) ? *(const float4*)&x[(size_t)rA[j] * IN_ + k0] : f4z;
                    bv[j] = *(const float4*)&wg[(size_t)(n0 + rowA) * IN_ + k0];
                }
            }

            // ---- compute chunk t: 4 k16 steps, 3-product bf16 split ----
            const uint32_t ah_b = sm_b + (uint32_t)(t & 1) * BUFSZ + a_off;
            const uint32_t al_b = ah_b + PLANE;
            const uint32_t bh_b = sm_b + (uint32_t)(t & 1) * BUFSZ + 2 * PLANE;
            const uint32_t bl_b = bh_b + PLANE;
            #pragma unroll
            for (int s = 0; s < 4; s++) {
                uint32_t koff = ((uint32_t)(khalf + s * 32)) ^ swx;
                uint32_t ah[4], al[4], bh0[4], bh1[4], bl0[4], bl1[4];
                ldsm4(ah,  ah_b + koff);
                ldsm4(al,  al_b + koff);
                ldsm4(bh0, bh_b + b0_off + koff);
                ldsm4(bh1, bh_b + b1_off + koff);
                ldsm4(bl0, bl_b + b0_off + koff);
                ldsm4(bl1, bl_b + b1_off + koff);

                uint32_t bhx[4][2] = {{bh0[0], bh0[2]}, {bh0[1], bh0[3]},
                                      {bh1[0], bh1[2]}, {bh1[1], bh1[3]}};
                uint32_t blx[4][2] = {{bl0[0], bl0[2]}, {bl0[1], bl0[3]},
                                      {bl1[0], bl1[2]}, {bl1[1], bl1[3]}};
                #pragma unroll
                for (int nf = 0; nf < 4; nf++) {
                    mma_bf16(acc[nf], ah, bhx[nf][0], bhx[nf][1]);  // hi*hi
                    mma_bf16(acc[nf], ah, blx[nf][0], blx[nf][1]);  // hi*lo
                    mma_bf16(acc[nf], al, bhx[nf][0], bhx[nf][1]);  // lo*hi
                }
            }
            // no trailing sync: next stage targets the other buffer; the
            // per-chunk barrier proves all warps left compute(t-1).
        }

        // ---- epilogue: scatter rows with bias ----
        {
            int gq = lid >> 2, tq = lid & 3;
            int m_lo = m0 + warp_m * 16 + gq;
            int r0 = (m_lo     < cnt) ? rows_bank[m_lo]     : -1;
            int r1 = (m_lo + 8 < cnt) ? rows_bank[m_lo + 8] : -1;
            #pragma unroll
            for (int nf = 0; nf < 4; nf++) {
                int col = warp_n * 32 + nf * 8 + tq * 2;
                float bb0 = bias_s[col], bb1 = bias_s[col + 1];
                if (r0 >= 0) {
                    float2 v = make_float2(acc[nf][0] + bb0, acc[nf][1] + bb1);
                    *(float2*)&out[(size_t)r0 * OUT_ + n0 + col] = v;
                }
                if (r1 >= 0) {
                    float2 v = make_float2(acc[nf][2] + bb0, acc[nf][3] + bb1);
                    *(float2*)&out[(size_t)r1 * OUT_ + n0 + col] = v;
                }
            }
        }
        __syncthreads();   // buffers free before any next m-pass staging
    }
}

// ---------------------------------------------------------------------------
extern "C" void kernel_launch(void* const* d_in, const int* in_sizes, int n_in,
                              void* d_out, int out_size) {
    const float* tensor = (const float*)d_in[0];   // (B,S,K,IN) fp32
    const int*   sel    = (const int*)  d_in[1];   // (B,S,K) int32
    const float* weight = (const float*)d_in[2];   // (NB,OUT,IN) fp32
    const float* bias   = (const float*)d_in[3];   // (NB,OUT) fp32
    float*       out    = (float*)d_out;           // (B,S,K,OUT) fp32

    cudaFuncSetAttribute(gemm_kernel, cudaFuncAttributeMaxDynamicSharedMemorySize, SMEM_TOTAL);
    dim3 grid(OUT_ / TN, NB_, 2);   // (8, 16, 2) = 256 CTAs, 2 CTA/SM, one wave
    gemm_kernel<<<grid, NTHREADS, SMEM_TOTAL>>>(tensor, sel, weight, bias, out);
}

// round 11
// speedup vs baseline: 1.5200x; 1.5200x over previous
#include <cuda_runtime.h>
#include <cuda_bf16.h>
#include <cstdint>

#define IN_      512
#define OUT_     512
#define NB_      16
#define M_TOTAL  1024
#define TM       64
#define TN       64
#define NTHREADS 256
#define NCHUNK   (IN_ / 64)    // 8

// dynamic smem layout (bytes)
#define PLANE     8192                    // 64 rows * 128 B (64 bf16/row)
#define BUF_BYTES (4 * PLANE)             // Ah, Al, Bh, Bl planes
#define OFF_ROWS  (2 * BUF_BYTES)         // 65536: int rows_bank[1024]
#define OFF_BIAS  (OFF_ROWS + M_TOTAL * 4)// 69632: float bias_s[64]
#define SMEM_TOTAL (OFF_BIAS + TN * 4)    // 69888

// ---------------- PTX helpers ----------------
__device__ __forceinline__ uint32_t smem_u32(const void* p) {
    uint32_t a;
    asm("{ .reg .u64 t; cvta.to.shared.u64 t, %1; cvt.u32.u64 %0, t; }" : "=r"(a) : "l"(p));
    return a;
}
__device__ __forceinline__ void ldsm4(uint32_t* r, uint32_t addr) {
    asm volatile("ldmatrix.sync.aligned.m8n8.x4.shared.b16 {%0,%1,%2,%3}, [%4];"
        : "=r"(r[0]), "=r"(r[1]), "=r"(r[2]), "=r"(r[3]) : "r"(addr));
}
__device__ __forceinline__ void mma_bf16(float* c, const uint32_t* a, uint32_t b0, uint32_t b1) {
    asm volatile("mma.sync.aligned.m16n8k16.row.col.f32.bf16.bf16.f32 "
        "{%0,%1,%2,%3}, {%4,%5,%6,%7}, {%8,%9}, {%0,%1,%2,%3};"
        : "+f"(c[0]), "+f"(c[1]), "+f"(c[2]), "+f"(c[3])
        : "r"(a[0]), "r"(a[1]), "r"(a[2]), "r"(a[3]), "r"(b0), "r"(b1));
}

// split float4 into bf16-hi (rounded) and bf16-lo (residual) packed pairs
// (R5's intrinsic version — the best-measured configuration)
__device__ __forceinline__ void split4(float4 v, uint2& hi, uint2& lo) {
    __nv_bfloat16 hx = __float2bfloat16_rn(v.x);
    __nv_bfloat16 hy = __float2bfloat16_rn(v.y);
    __nv_bfloat16 hz = __float2bfloat16_rn(v.z);
    __nv_bfloat16 hw = __float2bfloat16_rn(v.w);
    float rx = v.x - __bfloat162float(hx);
    float ry = v.y - __bfloat162float(hy);
    float rz = v.z - __bfloat162float(hz);
    float rw = v.w - __bfloat162float(hw);
    __nv_bfloat162 h01 = __halves2bfloat162(hx, hy);
    __nv_bfloat162 h23 = __halves2bfloat162(hz, hw);
    __nv_bfloat162 l01 = __halves2bfloat162(__float2bfloat16_rn(rx), __float2bfloat16_rn(ry));
    __nv_bfloat162 l23 = __halves2bfloat162(__float2bfloat16_rn(rz), __float2bfloat16_rn(rw));
    hi.x = *reinterpret_cast<uint32_t*>(&h01);
    hi.y = *reinterpret_cast<uint32_t*>(&h23);
    lo.x = *reinterpret_cast<uint32_t*>(&l01);
    lo.y = *reinterpret_cast<uint32_t*>(&l23);
}

// ---------------- fused binning + grouped GEMM (bf16-split HMMA) -------------
__global__ __launch_bounds__(NTHREADS, 2) void gemm_kernel(
    const float* __restrict__ x,      // (1024, IN)
    const int*   __restrict__ sel,    // (1024,)
    const float* __restrict__ w,      // (NB, OUT, IN)
    const float* __restrict__ bias,   // (NB, OUT)
    float* __restrict__ out)          // (1024, OUT)
{
    extern __shared__ __align__(128) uint8_t smem[];
    int*   rows_bank = (int*)(smem + OFF_ROWS);
    float* bias_s    = (float*)(smem + OFF_BIAS);
    __shared__ int warp_base[8];
    __shared__ int cnt_s;

    const int tid = threadIdx.x;
    const int lid = tid & 31, wid = tid >> 5;
    const int warp_m = wid & 3;        // 4 m-warps x 16 rows
    const int warp_n = wid >> 2;       // 2 n-warps x 32 cols
    const int g  = blockIdx.y;
    const int n0 = blockIdx.x * TN;
    const int mz = blockIdx.z;         // m-slice within bank

    // ---- deterministic binning: stable compaction of rows with sel==g ----
    {
        int4 sv = *(const int4*)&sel[tid * 4];
        int m0f = (sv.x == g), m1f = (sv.y == g), m2f = (sv.z == g), m3f = (sv.w == g);
        int lc = m0f + m1f + m2f + m3f;
        int inc = lc;
        #pragma unroll
        for (int d = 1; d < 32; d <<= 1) {
            int nv = __shfl_up_sync(0xffffffffu, inc, d);
            if (lid >= d) inc += nv;
        }
        if (lid == 31) warp_base[wid] = inc;
        __syncthreads();
        if (tid == 0) {
            int acc = 0;
            #pragma unroll
            for (int i = 0; i < 8; i++) { int v = warp_base[i]; warp_base[i] = acc; acc += v; }
            cnt_s = acc;
        }
        __syncthreads();
        int p = warp_base[wid] + inc - lc;   // exclusive rank
        if (m0f) rows_bank[p++] = tid * 4 + 0;
        if (m1f) rows_bank[p++] = tid * 4 + 1;
        if (m2f) rows_bank[p++] = tid * 4 + 2;
        if (m3f) rows_bank[p++] = tid * 4 + 3;
    }
    if (tid < TN) bias_s[tid] = bias[g * OUT_ + n0 + tid];
    __syncthreads();
    const int cnt = cnt_s;
    if (mz * TM >= cnt) return;

    const float* __restrict__ wg = w + (size_t)g * OUT_ * IN_;
    const uint32_t sm_b = smem_u32(smem);

    // staging geometry: 4 rows per thread (stride 16), 4 floats each (R5)
    const int rbase = tid >> 4;                       // 0..15
    const int c4    = (tid & 15) * 4;                 // k offset (floats)
    const uint32_t st_sw = (uint32_t)((tid & 15) * 8) ^ (uint32_t)((rbase & 7) * 16);

    // ldmatrix constant address parts (R5)
    const uint32_t swx   = (uint32_t)(lid & 7) * 16;
    const uint32_t khalf = (uint32_t)(lid >> 4) * 16;
    const uint32_t a_off  = (uint32_t)(warp_m * 16 + (lid & 15)) * 128;
    const uint32_t b0_off = (uint32_t)(warp_n * 32 + (lid & 15)) * 128;
    const uint32_t b1_off = b0_off + 16 * 128;

    const float4 f4z = make_float4(0.f, 0.f, 0.f, 0.f);

    for (int m0 = mz * TM; m0 < cnt; m0 += 2 * TM) {
        int rA[4];
        #pragma unroll
        for (int j = 0; j < 4; j++) {
            int m = m0 + rbase + j * 16;
            rA[j] = (m < cnt) ? rows_bank[m] : -1;
        }

        float4 av[4], bv[4];
        #pragma unroll
        for (int j = 0; j < 4; j++) {   // prefetch chunk 0
            int rowA = rbase + j * 16;
            av[j] = (rA[j] >= 0) ? *(const float4*)&x[(size_t)rA[j] * IN_ + c4] : f4z;
            bv[j] = *(const float4*)&wg[(size_t)(n0 + rowA) * IN_ + c4];
        }

        float acc[4][4] = {};

        #pragma unroll 1
        for (int t = 0; t < NCHUNK; t++) {            // 8 k-chunks of 64
            const uint32_t bufB = (uint32_t)(t & 1) * BUF_BYTES;
            uint8_t* bb = smem + bufB;

            // ---- stage chunk t into bf16 hi/lo planes of buf[t&1] (R5 pattern) ----
            #pragma unroll
            for (int j = 0; j < 4; j++) {
                uint32_t soff = (uint32_t)(rbase + j * 16) * 128 + st_sw;
                uint2 hi, lo;
                split4(av[j], hi, lo);
                *(uint2*)(bb + soff)          = hi;   // Ah
                *(uint2*)(bb + PLANE + soff)  = lo;   // Al
                split4(bv[j], hi, lo);
                *(uint2*)(bb + 2 * PLANE + soff) = hi; // Bh
                *(uint2*)(bb + 3 * PLANE + soff) = lo; // Bl
            }

            // ---- CHANGE 2: issue LDG(t+1) BEFORE the barrier ----
            if (t < NCHUNK - 1) {
                int k0 = (t + 1) * 64 + c4;
                #pragma unroll
                for (int j = 0; j < 4; j++) {
                    int rowA = rbase + j * 16;
                    av[j] = (rA[j] >= 0) ? *(const float4*)&x[(size_t)rA[j] * IN_ + k0] : f4z;
                    bv[j] = *(const float4*)&wg[(size_t)(n0 + rowA) * IN_ + k0];
                }
            }
            __syncthreads();   // one barrier per chunk (double-buffered)

            // ---- compute chunk t: 4 k16 steps ----
            const uint32_t ah_b = sm_b + bufB + a_off;
            const uint32_t al_b = ah_b + PLANE;
            const uint32_t bh_b = sm_b + bufB + 2 * PLANE;
            const uint32_t bl_b = bh_b + PLANE;
            #pragma unroll
            for (int s = 0; s < 4; s++) {
                uint32_t koff = ((uint32_t)(khalf + s * 32)) ^ swx;
                uint32_t ah[4], al[4], bh0[4], bh1[4], bl0[4], bl1[4];
                ldsm4(ah,  ah_b + koff);
                ldsm4(al,  al_b + koff);
                ldsm4(bh0, bh_b + b0_off + koff);
                ldsm4(bh1, bh_b + b1_off + koff);
                ldsm4(bl0, bl_b + b0_off + koff);
                ldsm4(bl1, bl_b + b1_off + koff);

                uint32_t bhx[4][2] = {{bh0[0], bh0[2]}, {bh0[1], bh0[3]},
                                      {bh1[0], bh1[2]}, {bh1[1], bh1[3]}};
                uint32_t blx[4][2] = {{bl0[0], bl0[2]}, {bl0[1], bl0[3]},
                                      {bl1[0], bl1[2]}, {bl1[1], bl1[3]}};
                // ---- CHANGE 1: product-major ordering (RAW distance 4) ----
                #pragma unroll
                for (int nf = 0; nf < 4; nf++)   // hi*hi: 4 independent MMAs
                    mma_bf16(acc[nf], ah, bhx[nf][0], bhx[nf][1]);
                #pragma unroll
                for (int nf = 0; nf < 4; nf++)   // hi*lo
                    mma_bf16(acc[nf], ah, blx[nf][0], blx[nf][1]);
                #pragma unroll
                for (int nf = 0; nf < 4; nf++)   // lo*hi
                    mma_bf16(acc[nf], al, bhx[nf][0], bhx[nf][1]);
            }
            // no trailing sync: next stage writes the other buffer, and the
            // per-iteration barrier proves all warps left compute(t-1).
        }

        // ---- epilogue: scatter rows with bias ----
        {
            int gq = lid >> 2, tq = lid & 3;
            int m_lo = m0 + warp_m * 16 + gq;
            int r0 = (m_lo     < cnt) ? rows_bank[m_lo]     : -1;
            int r1 = (m_lo + 8 < cnt) ? rows_bank[m_lo + 8] : -1;
            #pragma unroll
            for (int nf = 0; nf < 4; nf++) {
                int col = warp_n * 32 + nf * 8 + tq * 2;
                float bb0 = bias_s[col], bb1 = bias_s[col + 1];
                if (r0 >= 0) {
                    float2 v = make_float2(acc[nf][0] + bb0, acc[nf][1] + bb1);
                    *(float2*)&out[(size_t)r0 * OUT_ + n0 + col] = v;
                }
                if (r1 >= 0) {
                    float2 v = make_float2(acc[nf][2] + bb0, acc[nf][3] + bb1);
                    *(float2*)&out[(size_t)r1 * OUT_ + n0 + col] = v;
                }
            }
        }
    }
}

// ---------------------------------------------------------------------------
extern "C" void kernel_launch(void* const* d_in, const int* in_sizes, int n_in,
                              void* d_out, int out_size) {
    const float* tensor = (const float*)d_in[0];   // (B,S,K,IN) fp32
    const int*   sel    = (const int*)  d_in[1];   // (B,S,K) int32
    const float* weight = (const float*)d_in[2];   // (NB,OUT,IN) fp32
    const float* bias   = (const float*)d_in[3];   // (NB,OUT) fp32
    float*       out    = (float*)d_out;           // (B,S,K,OUT) fp32

    cudaFuncSetAttribute(gemm_kernel, cudaFuncAttributeMaxDynamicSharedMemorySize, SMEM_TOTAL);
    dim3 grid(OUT_ / TN, NB_, 2);   // (8, 16, 2) = 256 CTAs, 2 CTA/SM, one wave
    gemm_kernel<<<grid, NTHREADS, SMEM_TOTAL>>>(tensor, sel, weight, bias, out);
}

// round 12
// speedup vs baseline: 2.2353x; 1.4706x over previous
#include <cuda_runtime.h>
#include <cuda_fp16.h>
#include <cstdint>

#define IN_      512
#define OUT_     512
#define NB_      16
#define M_TOTAL  1024
#define TM       64
#define TN       64
#define NTHREADS 256
#define NCHUNK   (IN_ / 64)    // 8

// dynamic smem layout (bytes): per buffer: A plane + B plane (fp16)
#define PLANE     8192                    // 64 rows * 128 B (64 fp16/row)
#define BUF_BYTES (2 * PLANE)             // A, B planes
#define OFF_ROWS  (2 * BUF_BYTES)         // 32768: int rows_bank[1024]
#define OFF_BIAS  (OFF_ROWS + M_TOTAL * 4)
#define SMEM_TOTAL (OFF_BIAS + TN * 4)    // 37120

// ---------------- PTX helpers ----------------
__device__ __forceinline__ uint32_t smem_u32(const void* p) {
    uint32_t a;
    asm("{ .reg .u64 t; cvta.to.shared.u64 t, %1; cvt.u32.u64 %0, t; }" : "=r"(a) : "l"(p));
    return a;
}
__device__ __forceinline__ void ldsm4(uint32_t* r, uint32_t addr) {
    asm volatile("ldmatrix.sync.aligned.m8n8.x4.shared.b16 {%0,%1,%2,%3}, [%4];"
        : "=r"(r[0]), "=r"(r[1]), "=r"(r[2]), "=r"(r[3]) : "r"(addr));
}
__device__ __forceinline__ void mma_fp16(float* c, const uint32_t* a, uint32_t b0, uint32_t b1) {
    asm volatile("mma.sync.aligned.m16n8k16.row.col.f32.f16.f16.f32 "
        "{%0,%1,%2,%3}, {%4,%5,%6,%7}, {%8,%9}, {%0,%1,%2,%3};"
        : "+f"(c[0]), "+f"(c[1]), "+f"(c[2]), "+f"(c[3])
        : "r"(a[0]), "r"(a[1]), "r"(a[2]), "r"(a[3]), "r"(b0), "r"(b1));
}

// pack float4 -> 2x fp16x2 (rn)
__device__ __forceinline__ uint2 pack4_f16(float4 v) {
    __half2 p01 = __floats2half2_rn(v.x, v.y);
    __half2 p23 = __floats2half2_rn(v.z, v.w);
    uint2 r;
    r.x = *reinterpret_cast<uint32_t*>(&p01);
    r.y = *reinterpret_cast<uint32_t*>(&p23);
    return r;
}

// ---------------- fused binning + grouped GEMM (fp16 HMMA) -------------------
__global__ __launch_bounds__(NTHREADS, 2) void gemm_kernel(
    const float* __restrict__ x,      // (1024, IN)
    const int*   __restrict__ sel,    // (1024,)
    const float* __restrict__ w,      // (NB, OUT, IN)
    const float* __restrict__ bias,   // (NB, OUT)
    float* __restrict__ out)          // (1024, OUT)
{
    extern __shared__ __align__(128) uint8_t smem[];
    int*   rows_bank = (int*)(smem + OFF_ROWS);
    float* bias_s    = (float*)(smem + OFF_BIAS);
    __shared__ int warp_base[8];
    __shared__ int cnt_s;

    const int tid = threadIdx.x;
    const int lid = tid & 31, wid = tid >> 5;
    const int warp_m = wid & 3;        // 4 m-warps x 16 rows
    const int warp_n = wid >> 2;       // 2 n-warps x 32 cols
    const int g  = blockIdx.y;
    const int n0 = blockIdx.x * TN;
    const int mz = blockIdx.z;         // m-slice within bank

    // ---- deterministic binning: stable compaction of rows with sel==g ----
    {
        int4 sv = *(const int4*)&sel[tid * 4];
        int m0f = (sv.x == g), m1f = (sv.y == g), m2f = (sv.z == g), m3f = (sv.w == g);
        int lc = m0f + m1f + m2f + m3f;
        int inc = lc;
        #pragma unroll
        for (int d = 1; d < 32; d <<= 1) {
            int nv = __shfl_up_sync(0xffffffffu, inc, d);
            if (lid >= d) inc += nv;
        }
        if (lid == 31) warp_base[wid] = inc;
        __syncthreads();
        if (tid == 0) {
            int acc = 0;
            #pragma unroll
            for (int i = 0; i < 8; i++) { int v = warp_base[i]; warp_base[i] = acc; acc += v; }
            cnt_s = acc;
        }
        __syncthreads();
        int p = warp_base[wid] + inc - lc;   // exclusive rank
        if (m0f) rows_bank[p++] = tid * 4 + 0;
        if (m1f) rows_bank[p++] = tid * 4 + 1;
        if (m2f) rows_bank[p++] = tid * 4 + 2;
        if (m3f) rows_bank[p++] = tid * 4 + 3;
    }
    if (tid < TN) bias_s[tid] = bias[g * OUT_ + n0 + tid];
    __syncthreads();
    const int cnt = cnt_s;
    if (mz * TM >= cnt) return;

    const float* __restrict__ wg = w + (size_t)g * OUT_ * IN_;
    const uint32_t sm_b = smem_u32(smem);

    // staging geometry: 4 rows per thread (stride 16), 4 floats each (R5/R11)
    const int rbase = tid >> 4;                       // 0..15
    const int c4    = (tid & 15) * 4;                 // k offset (floats)
    const uint32_t st_sw = (uint32_t)((tid & 15) * 8) ^ (uint32_t)((rbase & 7) * 16);

    // ldmatrix constant address parts (R5/R11)
    const uint32_t swx   = (uint32_t)(lid & 7) * 16;
    const uint32_t khalf = (uint32_t)(lid >> 4) * 16;
    const uint32_t a_off  = (uint32_t)(warp_m * 16 + (lid & 15)) * 128;
    const uint32_t b0_off = (uint32_t)(warp_n * 32 + (lid & 15)) * 128;
    const uint32_t b1_off = b0_off + 16 * 128;

    const float4 f4z = make_float4(0.f, 0.f, 0.f, 0.f);

    for (int m0 = mz * TM; m0 < cnt; m0 += 2 * TM) {
        int rA[4];
        #pragma unroll
        for (int j = 0; j < 4; j++) {
            int m = m0 + rbase + j * 16;
            rA[j] = (m < cnt) ? rows_bank[m] : -1;
        }

        float4 av[4], bv[4];
        #pragma unroll
        for (int j = 0; j < 4; j++) {   // prefetch chunk 0
            int rowA = rbase + j * 16;
            av[j] = (rA[j] >= 0) ? *(const float4*)&x[(size_t)rA[j] * IN_ + c4] : f4z;
            bv[j] = *(const float4*)&wg[(size_t)(n0 + rowA) * IN_ + c4];
        }

        float acc[4][4] = {};

        #pragma unroll 1
        for (int t = 0; t < NCHUNK; t++) {            // 8 k-chunks of 64
            const uint32_t bufB = (uint32_t)(t & 1) * BUF_BYTES;
            uint8_t* bb = smem + bufB;

            // ---- stage chunk t into fp16 planes of buf[t&1] ----
            #pragma unroll
            for (int j = 0; j < 4; j++) {
                uint32_t soff = (uint32_t)(rbase + j * 16) * 128 + st_sw;
                *(uint2*)(bb + soff)         = pack4_f16(av[j]);   // A
                *(uint2*)(bb + PLANE + soff) = pack4_f16(bv[j]);   // B
            }

            // ---- issue LDG(t+1) before the barrier ----
            if (t < NCHUNK - 1) {
                int k0 = (t + 1) * 64 + c4;
                #pragma unroll
                for (int j = 0; j < 4; j++) {
                    int rowA = rbase + j * 16;
                    av[j] = (rA[j] >= 0) ? *(const float4*)&x[(size_t)rA[j] * IN_ + k0] : f4z;
                    bv[j] = *(const float4*)&wg[(size_t)(n0 + rowA) * IN_ + k0];
                }
            }
            __syncthreads();   // one barrier per chunk (double-buffered)

            // ---- compute chunk t: 4 k16 steps, single fp16 product ----
            const uint32_t a_b = sm_b + bufB + a_off;
            const uint32_t b_b = sm_b + bufB + PLANE;
            #pragma unroll
            for (int s = 0; s < 4; s++) {
                uint32_t koff = ((uint32_t)(khalf + s * 32)) ^ swx;
                uint32_t ah[4], bh0[4], bh1[4];
                ldsm4(ah,  a_b + koff);
                ldsm4(bh0, b_b + b0_off + koff);
                ldsm4(bh1, b_b + b1_off + koff);

                uint32_t bx[4][2] = {{bh0[0], bh0[2]}, {bh0[1], bh0[3]},
                                     {bh1[0], bh1[2]}, {bh1[1], bh1[3]}};
                #pragma unroll
                for (int nf = 0; nf < 4; nf++)
                    mma_fp16(acc[nf], ah, bx[nf][0], bx[nf][1]);
            }
            // no trailing sync: next stage writes the other buffer; the
            // per-iteration barrier proves all warps left compute(t-1).
        }

        // ---- epilogue: scatter rows with bias ----
        {
            int gq = lid >> 2, tq = lid & 3;
            int m_lo = m0 + warp_m * 16 + gq;
            int r0 = (m_lo     < cnt) ? rows_bank[m_lo]     : -1;
            int r1 = (m_lo + 8 < cnt) ? rows_bank[m_lo + 8] : -1;
            #pragma unroll
            for (int nf = 0; nf < 4; nf++) {
                int col = warp_n * 32 + nf * 8 + tq * 2;
                float bb0 = bias_s[col], bb1 = bias_s[col + 1];
                if (r0 >= 0) {
                    float2 v = make_float2(acc[nf][0] + bb0, acc[nf][1] + bb1);
                    *(float2*)&out[(size_t)r0 * OUT_ + n0 + col] = v;
                }
                if (r1 >= 0) {
                    float2 v = make_float2(acc[nf][2] + bb0, acc[nf][3] + bb1);
                    *(float2*)&out[(size_t)r1 * OUT_ + n0 + col] = v;
                }
            }
        }
    }
}

// ---------------------------------------------------------------------------
extern "C" void kernel_launch(void* const* d_in, const int* in_sizes, int n_in,
                              void* d_out, int out_size) {
    const float* tensor = (const float*)d_in[0];   // (B,S,K,IN) fp32
    const int*   sel    = (const int*)  d_in[1];   // (B,S,K) int32
    const float* weight = (const float*)d_in[2];   // (NB,OUT,IN) fp32
    const float* bias   = (const float*)d_in[3];   // (NB,OUT) fp32
    float*       out    = (float*)d_out;           // (B,S,K,OUT) fp32

    cudaFuncSetAttribute(gemm_kernel, cudaFuncAttributeMaxDynamicSharedMemorySize, SMEM_TOTAL);
    dim3 grid(OUT_ / TN, NB_, 2);   // (8, 16, 2) = 256 CTAs, 2 CTA/SM, one wave
    gemm_kernel<<<grid, NTHREADS, SMEM_TOTAL>>>(tensor, sel, weight, bias, out);
}

// round 13
// speedup vs baseline: 2.2800x; 1.0200x over previous
#include <cuda_runtime.h>
#include <cuda_fp16.h>
#include <cstdint>

#define IN_      512
#define OUT_     512
#define NB_      16
#define M_TOTAL  1024
#define TM       32
#define TN       32
#define NTHREADS 128
#define NWARPS   4
#define NCHUNK   (IN_ / 64)    // 8

// smem: 2 buffers x (A plane + B plane), fp16, 32 rows x 128B each
#define PLANE      4096
#define BUF_BYTES  (2 * PLANE)              // 8 KB
#define OFF_ROWS   (2 * BUF_BYTES)          // 16384: int rows_bank[1024]
#define OFF_BIAS   (OFF_ROWS + M_TOTAL * 4) // 20480
#define SMEM_TOTAL (OFF_BIAS + TN * 4)      // 20608

// ---------------- PTX helpers ----------------
__device__ __forceinline__ uint32_t smem_u32(const void* p) {
    uint32_t a;
    asm("{ .reg .u64 t; cvta.to.shared.u64 t, %1; cvt.u32.u64 %0, t; }" : "=r"(a) : "l"(p));
    return a;
}
__device__ __forceinline__ void ldsm4(uint32_t* r, uint32_t addr) {
    asm volatile("ldmatrix.sync.aligned.m8n8.x4.shared.b16 {%0,%1,%2,%3}, [%4];"
        : "=r"(r[0]), "=r"(r[1]), "=r"(r[2]), "=r"(r[3]) : "r"(addr));
}
__device__ __forceinline__ void mma_fp16(float* c, const uint32_t* a, uint32_t b0, uint32_t b1) {
    asm volatile("mma.sync.aligned.m16n8k16.row.col.f32.f16.f16.f32 "
        "{%0,%1,%2,%3}, {%4,%5,%6,%7}, {%8,%9}, {%0,%1,%2,%3};"
        : "+f"(c[0]), "+f"(c[1]), "+f"(c[2]), "+f"(c[3])
        : "r"(a[0]), "r"(a[1]), "r"(a[2]), "r"(a[3]), "r"(b0), "r"(b1));
}
__device__ __forceinline__ uint2 pack4_f16(float4 v) {
    __half2 p01 = __floats2half2_rn(v.x, v.y);
    __half2 p23 = __floats2half2_rn(v.z, v.w);
    uint2 r;
    r.x = *reinterpret_cast<uint32_t*>(&p01);
    r.y = *reinterpret_cast<uint32_t*>(&p23);
    return r;
}

// ---------------- fused binning + grouped GEMM (fp16 HMMA) -------------------
__global__ __launch_bounds__(NTHREADS, 5) void gemm_kernel(
    const float* __restrict__ x,      // (1024, IN)
    const int*   __restrict__ sel,    // (1024,)
    const float* __restrict__ w,      // (NB, OUT, IN)
    const float* __restrict__ bias,   // (NB, OUT)
    float* __restrict__ out)          // (1024, OUT)
{
    extern __shared__ __align__(128) uint8_t smem[];
    int*   rows_bank = (int*)(smem + OFF_ROWS);
    float* bias_s    = (float*)(smem + OFF_BIAS);
    __shared__ int warp_base[NWARPS];
    __shared__ int cnt_s;

    const int tid = threadIdx.x;
    const int lid = tid & 31, wid = tid >> 5;
    const int warp_m = wid & 1;        // 2 m-warps x 16 rows
    const int warp_n = wid >> 1;       // 2 n-warps x 16 cols
    const int g  = blockIdx.y;
    const int n0 = blockIdx.x * TN;
    const int mz = blockIdx.z;         // m-slice within bank (4 slices of 32)

    // ---- deterministic binning: stable compaction, 8 sel values per thread ----
    {
        int4 s0 = *(const int4*)&sel[tid * 8];
        int4 s1 = *(const int4*)&sel[tid * 8 + 4];
        int f0 = (s0.x == g), f1 = (s0.y == g), f2 = (s0.z == g), f3 = (s0.w == g);
        int f4 = (s1.x == g), f5 = (s1.y == g), f6 = (s1.z == g), f7 = (s1.w == g);
        int lc = f0 + f1 + f2 + f3 + f4 + f5 + f6 + f7;
        int inc = lc;
        #pragma unroll
        for (int d = 1; d < 32; d <<= 1) {
            int nv = __shfl_up_sync(0xffffffffu, inc, d);
            if (lid >= d) inc += nv;
        }
        if (lid == 31) warp_base[wid] = inc;
        __syncthreads();
        if (tid == 0) {
            int acc = 0;
            #pragma unroll
            for (int i = 0; i < NWARPS; i++) { int v = warp_base[i]; warp_base[i] = acc; acc += v; }
            cnt_s = acc;
        }
        __syncthreads();
        int p = warp_base[wid] + inc - lc;   // exclusive rank
        int b = tid * 8;
        if (f0) rows_bank[p++] = b + 0;
        if (f1) rows_bank[p++] = b + 1;
        if (f2) rows_bank[p++] = b + 2;
        if (f3) rows_bank[p++] = b + 3;
        if (f4) rows_bank[p++] = b + 4;
        if (f5) rows_bank[p++] = b + 5;
        if (f6) rows_bank[p++] = b + 6;
        if (f7) rows_bank[p++] = b + 7;
    }
    if (tid < TN) bias_s[tid] = bias[g * OUT_ + n0 + tid];
    __syncthreads();
    const int cnt = cnt_s;
    if (mz * TM >= cnt) return;

    const float* __restrict__ wg = w + (size_t)g * OUT_ * IN_;
    const uint32_t sm_b = smem_u32(smem);

    // staging geometry: 16 threads sweep one 128B row; 8 rows per sweep,
    // 4 sweeps cover 32 rows. rbase = tid>>4 in 0..7 (row & 7 == rbase).
    const int rbase = tid >> 4;                       // 0..7
    const int c4    = (tid & 15) * 4;                 // k offset (floats)
    const uint32_t st_sw = (uint32_t)((tid & 15) * 8) ^ (uint32_t)(rbase * 16);

    // ldmatrix constant address parts
    const uint32_t swx   = (uint32_t)(lid & 7) * 16;
    const uint32_t khalf = (uint32_t)(lid >> 4) * 16;
    const uint32_t a_off = (uint32_t)(warp_m * 16 + (lid & 15)) * 128;
    const uint32_t b_off = (uint32_t)(warp_n * 16 + (lid & 15)) * 128;

    const float4 f4z = make_float4(0.f, 0.f, 0.f, 0.f);

    for (int m0 = mz * TM; m0 < cnt; m0 += 4 * TM) {
        int rA[4];
        #pragma unroll
        for (int j = 0; j < 4; j++) {
            int m = m0 + rbase + j * 8;
            rA[j] = (m < cnt) ? rows_bank[m] : -1;
        }

        float4 av[4], bv[4];
        #pragma unroll
        for (int j = 0; j < 4; j++) {   // prefetch chunk 0
            int row = rbase + j * 8;
            av[j] = (rA[j] >= 0) ? *(const float4*)&x[(size_t)rA[j] * IN_ + c4] : f4z;
            bv[j] = *(const float4*)&wg[(size_t)(n0 + row) * IN_ + c4];
        }

        float acc[2][4] = {};

        #pragma unroll 1
        for (int t = 0; t < NCHUNK; t++) {            // 8 k-chunks of 64
            const uint32_t bufB = (uint32_t)(t & 1) * BUF_BYTES;
            uint8_t* bb = smem + bufB;

            // ---- stage chunk t into fp16 planes of buf[t&1] ----
            #pragma unroll
            for (int j = 0; j < 4; j++) {
                uint32_t soff = (uint32_t)((rbase + j * 8) * 128) + st_sw;
                *(uint2*)(bb + soff)         = pack4_f16(av[j]);   // A
                *(uint2*)(bb + PLANE + soff) = pack4_f16(bv[j]);   // B
            }

            // ---- issue LDG(t+1) before the barrier ----
            if (t < NCHUNK - 1) {
                int k0 = (t + 1) * 64 + c4;
                #pragma unroll
                for (int j = 0; j < 4; j++) {
                    int row = rbase + j * 8;
                    av[j] = (rA[j] >= 0) ? *(const float4*)&x[(size_t)rA[j] * IN_ + k0] : f4z;
                    bv[j] = *(const float4*)&wg[(size_t)(n0 + row) * IN_ + k0];
                }
            }
            __syncthreads();   // one barrier per chunk (double-buffered)

            // ---- compute chunk t: 4 k16 steps, 2 MMAs each ----
            const uint32_t a_b = sm_b + bufB + a_off;
            const uint32_t b_b = sm_b + bufB + PLANE + b_off;
            #pragma unroll
            for (int s = 0; s < 4; s++) {
                uint32_t koff = ((uint32_t)(khalf + s * 32)) ^ swx;
                uint32_t ah[4], bh[4];
                ldsm4(ah, a_b + koff);
                ldsm4(bh, b_b + koff);
                mma_fp16(acc[0], ah, bh[0], bh[2]);   // cols +0..7
                mma_fp16(acc[1], ah, bh[1], bh[3]);   // cols +8..15
            }
            // no trailing sync: next stage writes the other buffer; the
            // per-iteration barrier proves all warps left compute(t-1).
        }

        // ---- epilogue: scatter rows with bias ----
        {
            int gq = lid >> 2, tq = lid & 3;
            int m_lo = m0 + warp_m * 16 + gq;
            int r0 = (m_lo     < cnt) ? rows_bank[m_lo]     : -1;
            int r1 = (m_lo + 8 < cnt) ? rows_bank[m_lo + 8] : -1;
            #pragma unroll
            for (int nf = 0; nf < 2; nf++) {
                int col = warp_n * 16 + nf * 8 + tq * 2;
                float bb0 = bias_s[col], bb1 = bias_s[col + 1];
                if (r0 >= 0) {
                    float2 v = make_float2(acc[nf][0] + bb0, acc[nf][1] + bb1);
                    *(float2*)&out[(size_t)r0 * OUT_ + n0 + col] = v;
                }
                if (r1 >= 0) {
                    float2 v = make_float2(acc[nf][2] + bb0, acc[nf][3] + bb1);
                    *(float2*)&out[(size_t)r1 * OUT_ + n0 + col] = v;
                }
            }
        }
    }
}

// ---------------------------------------------------------------------------
extern "C" void kernel_launch(void* const* d_in, const int* in_sizes, int n_in,
                              void* d_out, int out_size) {
    const float* tensor = (const float*)d_in[0];   // (B,S,K,IN) fp32
    const int*   sel    = (const int*)  d_in[1];   // (B,S,K) int32
    const float* weight = (const float*)d_in[2];   // (NB,OUT,IN) fp32
    const float* bias   = (const float*)d_in[3];   // (NB,OUT) fp32
    float*       out    = (float*)d_out;           // (B,S,K,OUT) fp32

    cudaFuncSetAttribute(gemm_kernel, cudaFuncAttributeMaxDynamicSharedMemorySize, SMEM_TOTAL);
    dim3 grid(OUT_ / TN, NB_, 4);   // (16, 16, 4) = 1024 CTAs, ~5 CTA/SM capacity
    gemm_kernel<<<grid, NTHREADS, SMEM_TOTAL>>>(tensor, sel, weight, bias, out);
}